// round 2
// baseline (speedup 1.0000x reference)
#include <cuda_runtime.h>
#include <stdint.h>

// Problem constants (from reference):
//   BATCH = 128, BUFFER_SIZE = 16, H = W = 128, C = 3
//   IMG = H*W*C = 49152 floats per image (divisible by 4 -> 12288 float4)
//   out[i, k, :] = combined[i + 1 + k], combined = concat(buffer, inputs)

#define BATCH 128
#define KBUF 16
#define IMG 49152
#define IMG4 (IMG / 4)                  // 12288 float4 per image
#define TOTAL4 (BATCH * KBUF * IMG4)    // 25,165,824 float4 total

__global__ __launch_bounds__(256) void image_buffer_gather(
    const float4* __restrict__ inputs,   // [BATCH, IMG4]
    const float4* __restrict__ buffer,   // [KBUF, IMG4]
    float4* __restrict__ out)            // [BATCH*KBUF, IMG4]
{
    const int64_t u = (int64_t)blockIdx.x * blockDim.x + threadIdx.x;
    if (u >= (int64_t)TOTAL4) return;

    // m = output image index (i*16 + k), pos = float4 offset within image
    const int m   = (int)(u / IMG4);
    const int pos = (int)(u - (int64_t)m * IMG4);

    const int i = m >> 4;          // m / 16
    const int k = m & 15;          // m % 16
    const int j = i + 1 + k;       // combined index in [1, 143]

    const float4* src = (j < KBUF)
        ? (buffer + (int64_t)j * IMG4 + pos)
        : (inputs + (int64_t)(j - KBUF) * IMG4 + pos);

    out[u] = *src;
}

extern "C" void kernel_launch(void* const* d_in, const int* in_sizes, int n_in,
                              void* d_out, int out_size) {
    // metadata order: inputs [128,128,128,3] f32, buffer [16,128,128,3] f32
    const float4* inputs = (const float4*)d_in[0];
    const float4* buffer = (const float4*)d_in[1];
    float4* out = (float4*)d_out;

    const int threads = 256;
    const int blocks = (TOTAL4 + threads - 1) / threads;  // 98304
    image_buffer_gather<<<blocks, threads>>>(inputs, buffer, out);
}

// round 7
// speedup vs baseline: 1.0315x; 1.0315x over previous
#include <cuda_runtime.h>
#include <stdint.h>

// BATCH=128, BUFFER_SIZE=16, IMG = 128*128*3 = 49152 floats = 12288 float4
// out[m] = combined[m/16 + 1 + m%16], combined = concat(buffer, inputs)
//
// Grid: y = output image m (0..2047), x = chunk (0..5) of 2048 float4.
// Block: 256 threads; each thread moves 8 float4 at stride 256.
// Coverage per block: 256 threads * 8 offsets * stride 256 = [0, 2048). ✓

#define KBUF 16
#define IMG4 12288
#define CHUNK4 2048   // float4 per block (6 chunks per image)

__global__ __launch_bounds__(256) void image_buffer_gather(
    const float4* __restrict__ inputs,   // [128, IMG4]
    const float4* __restrict__ buffer,   // [16,  IMG4]
    float4* __restrict__ out)            // [2048, IMG4]
{
    const int m = blockIdx.y;            // output image index, 0..2047
    const int i = m >> 4;
    const int k = m & 15;
    const int j = i + 1 + k;             // combined index, 1..143 (block-uniform)

    const float4* __restrict__ srcimg = (j < KBUF)
        ? (buffer + j * IMG4)
        : (inputs + (j - KBUF) * IMG4);

    const int base = blockIdx.x * CHUNK4 + threadIdx.x;
    const float4* __restrict__ src = srcimg + base;
    float4* __restrict__ dst = out + (int64_t)m * IMG4 + base;

    // 8 independent loads (MLP=8), then 8 streaming stores (evict-first:
    // output is never re-read; keep L2 for the 16x-reused source images).
    float4 a0 = src[0 * 256];
    float4 a1 = src[1 * 256];
    float4 a2 = src[2 * 256];
    float4 a3 = src[3 * 256];
    float4 a4 = src[4 * 256];
    float4 a5 = src[5 * 256];
    float4 a6 = src[6 * 256];
    float4 a7 = src[7 * 256];
    __stcs(dst + 0 * 256, a0);
    __stcs(dst + 1 * 256, a1);
    __stcs(dst + 2 * 256, a2);
    __stcs(dst + 3 * 256, a3);
    __stcs(dst + 4 * 256, a4);
    __stcs(dst + 5 * 256, a5);
    __stcs(dst + 6 * 256, a6);
    __stcs(dst + 7 * 256, a7);
}

extern "C" void kernel_launch(void* const* d_in, const int* in_sizes, int n_in,
                              void* d_out, int out_size) {
    const float4* inputs = (const float4*)d_in[0];
    const float4* buffer = (const float4*)d_in[1];
    float4* out = (float4*)d_out;

    dim3 grid(6, 2048);   // 6 chunks x 2048 output images = 12288 blocks
    image_buffer_gather<<<grid, 256>>>(inputs, buffer, out);
}